// round 6
// baseline (speedup 1.0000x reference)
#include <cuda_runtime.h>
#include <cuda_bf16.h>

#define BS 2
#define NN 512
#define DD 128
#define JS 4            // j-splits in main GEMM
#define SZ (BS*NN*DD)   // 131072

typedef unsigned long long u64;

// ---------------- device scratch (no allocs allowed) ----------------
__device__ float g_sq[SZ];         // sigmoid(q)
__device__ float g_ek[SZ];         // exp(k)       (|k| <~ 5, safe unshifted)
__device__ float g_ev[SZ];         // exp(k) * v
__device__ float g_eB[NN*NN];      // exp(B)       (B ~ +-0.06)
__device__ float g_pn[JS*SZ];      // partial numerators
__device__ float g_pd[JS*SZ];      // partial denominators

// ---------------- f32x2 + cp.async helpers ----------------
__device__ __forceinline__ u64 pack2(float lo, float hi) {
    u64 r; asm("mov.b64 %0, {%1, %2};" : "=l"(r) : "f"(lo), "f"(hi)); return r;
}
__device__ __forceinline__ void ffma2(u64 &acc, u64 a, u64 b) {
    asm("fma.rn.f32x2 %0, %1, %2, %0;" : "+l"(acc) : "l"(a), "l"(b));
}
__device__ __forceinline__ float2 unpack2(u64 v) {
    float lo, hi; asm("mov.b64 {%0, %1}, %2;" : "=f"(lo), "=f"(hi) : "l"(v));
    return make_float2(lo, hi);
}
__device__ __forceinline__ void cp16(void* sdst, const void* gsrc) {
    unsigned s = (unsigned)__cvta_generic_to_shared(sdst);
    asm volatile("cp.async.ca.shared.global [%0], [%1], 16;" :: "r"(s), "l"(gsrc));
}
__device__ __forceinline__ void cp_commit() { asm volatile("cp.async.commit_group;"); }
template<int NPEND> __device__ __forceinline__ void cp_wait() {
    asm volatile("cp.async.wait_group %0;" :: "n"(NPEND));
}

// ---------------- shared GEMM pass: acc[4] = bias + x[16rows] @ W ----------------
// xs must already be staged & visible. Stages W in Ws double-buffer itself.
// 256 threads; thread tile 2 rows (rt, rt+8) x 4 cols.
__device__ __forceinline__ void gemm16(
    const float* __restrict__ W, const float* __restrict__ bias,
    const float* xs, float (*Ws)[32*128],
    int tid, int rt, int d, u64 acc[4])
{
    for (int q = tid; q < 32*128/4; q += 256) cp16(&Ws[0][q*4], &W[q*4]);
    cp_commit();

    const float4 bb = *(const float4*)&bias[d];
    acc[0] = pack2(bb.x, bb.y); acc[1] = pack2(bb.z, bb.w);
    acc[2] = acc[0];            acc[3] = acc[1];

    for (int cc = 0; cc < 128; cc += 32) {
        const int s = (cc >> 5) & 1;
        if (cc + 32 < 128) {
            const int sn = s ^ 1;
            const float* Wn = &W[(cc + 32) * 128];
            for (int q = tid; q < 32*128/4; q += 256) cp16(&Ws[sn][q*4], &Wn[q*4]);
            cp_commit();
            cp_wait<1>();
        } else {
            cp_wait<0>();
        }
        __syncthreads();
        #pragma unroll
        for (int c = 0; c < 32; ++c) {
            const u64* wrow = (const u64*)&Ws[s][c*128 + d];
            const u64 w01 = wrow[0], w23 = wrow[1];
            const float x0 = xs[rt*128 + cc + c];
            const float x1 = xs[(rt+8)*128 + cc + c];
            const u64 X0 = pack2(x0, x0), X1 = pack2(x1, x1);
            ffma2(acc[0], X0, w01); ffma2(acc[1], X0, w23);
            ffma2(acc[2], X1, w01); ffma2(acc[3], X1, w23);
        }
        __syncthreads();
    }
}

// ---------------- K1: projections + eB ----------------
// grid (64, 3), 256 threads.
//   y=0: k and v GEMMs (two passes) -> g_ek = exp(k), g_ev = exp(k)*v
//   y=1: q GEMM -> sigmoid -> g_sq
//   y=2: eB = exp(B) elementwise
__global__ __launch_bounds__(256) void proj_kernel(
    const float* __restrict__ x,
    const float* __restrict__ Wq, const float* __restrict__ bq,
    const float* __restrict__ Wk, const float* __restrict__ bk,
    const float* __restrict__ Wv, const float* __restrict__ bv,
    const float* __restrict__ Bm)
{
    __shared__ float xs[16*128];
    __shared__ float Ws[2][32*128];
    const int mat = blockIdx.y;
    const int tid = threadIdx.x;

    if (mat == 2) {
        #pragma unroll
        for (int r = 0; r < 4; ++r) {
            const int off = blockIdx.x * 4096 + r * 1024 + tid * 4;
            const float4 b4 = *(const float4*)&Bm[off];
            float4 e;
            e.x = __expf(b4.x); e.y = __expf(b4.y);
            e.z = __expf(b4.z); e.w = __expf(b4.w);
            *(float4*)&g_eB[off] = e;
        }
        return;
    }

    const int row0 = blockIdx.x * 16;
    const int dt = tid & 31, rt = tid >> 5;
    const int d = dt * 4;

    // stage x tile (its cp.async group completes with the first W group inside gemm16)
    for (int q = tid; q < 16*128/4; q += 256) cp16(&xs[q*4], &x[row0*128 + q*4]);

    if (mat == 1) {                        // q
        u64 aq[4];
        gemm16(Wq, bq, xs, Ws, tid, rt, d, aq);
        #pragma unroll
        for (int r = 0; r < 2; ++r) {
            const int grow = row0 + ((r == 0) ? rt : (rt + 8));
            const float2 p = unpack2(aq[r*2]), q2 = unpack2(aq[r*2+1]);
            float4 o;
            o.x = 1.f/(1.f+__expf(-p.x));  o.y = 1.f/(1.f+__expf(-p.y));
            o.z = 1.f/(1.f+__expf(-q2.x)); o.w = 1.f/(1.f+__expf(-q2.y));
            *(float4*)&g_sq[grow*128 + d] = o;
        }
    } else {                               // k then v
        u64 ak[4], av[4];
        gemm16(Wk, bk, xs, Ws, tid, rt, d, ak);
        gemm16(Wv, bv, xs, Ws, tid, rt, d, av);
        #pragma unroll
        for (int r = 0; r < 2; ++r) {
            const int grow = row0 + ((r == 0) ? rt : (rt + 8));
            const float2 k01 = unpack2(ak[r*2]), k23 = unpack2(ak[r*2+1]);
            const float2 v01 = unpack2(av[r*2]), v23 = unpack2(av[r*2+1]);
            float4 ek, ev;
            ek.x = __expf(k01.x); ek.y = __expf(k01.y);
            ek.z = __expf(k23.x); ek.w = __expf(k23.y);
            ev.x = ek.x * v01.x;  ev.y = ek.y * v01.y;
            ev.z = ek.z * v23.x;  ev.w = ek.w * v23.y;
            *(float4*)&g_ek[grow*128 + d] = ek;
            *(float4*)&g_ev[grow*128 + d] = ev;
        }
    }
}

// ---------------- K2: partial GEMM  pn|pd += eB @ (ev | ek) ----------------
// grid (64, 2, 2): x = itile(16) * js(4), y = 64-d half, z = batch. 128 threads.
// CTA tile: 32 i x 64 d x 128 j. Thread tile: 4 i x 4 d, 16 f32x2 accumulators.
// cp.async double-buffered 32-j chunks.
__global__ __launch_bounds__(128) void aft_kernel()
{
    __shared__ float eBs[2][32][36];   // [i][j] padded
    __shared__ float evs[2][32][64];
    __shared__ float eks[2][32][64];
    const int jx  = blockIdx.x & 3;
    const int it0 = (blockIdx.x >> 2) * 32;
    const int jb  = jx * 128;
    const int d0  = blockIdx.y * 64;
    const int b   = blockIdx.z;
    const int tid = threadIdx.x;
    const int dt = tid & 15, rt = tid >> 4;
    const int d = dt * 4;
    const int i0 = rt * 4;
    const float* evb = g_ev + b*NN*DD + d0;
    const float* ekb = g_ek + b*NN*DD + d0;

    u64 aN[4][2], aD[4][2];
    #pragma unroll
    for (int ii = 0; ii < 4; ++ii) {
        aN[ii][0] = 0; aN[ii][1] = 0; aD[ii][0] = 0; aD[ii][1] = 0;
    }

    auto stage = [&](int s, int jc) {
        #pragma unroll
        for (int q = 0; q < 4; ++q) {
            const int e = tid + q*128;
            const int j = e >> 4, dd = (e & 15) * 4;
            cp16(&evs[s][j][dd], &evb[(jb + jc + j)*DD + dd]);
            cp16(&eks[s][j][dd], &ekb[(jb + jc + j)*DD + dd]);
        }
        const int ri = tid >> 2, c4 = (tid & 3) * 4;
        const float* src = &g_eB[(it0 + ri)*NN + jb + jc];
        cp16(&eBs[s][ri][c4],      &src[c4]);
        cp16(&eBs[s][ri][c4 + 16], &src[c4 + 16]);
    };

    stage(0, 0);
    cp_commit();

    for (int m = 0; m < 4; ++m) {
        const int s = m & 1;
        if (m + 1 < 4) { stage(s ^ 1, (m + 1)*32); cp_commit(); cp_wait<1>(); }
        else           { cp_wait<0>(); }
        __syncthreads();
        #pragma unroll 8
        for (int j = 0; j < 32; ++j) {
            const u64* vp = (const u64*)&evs[s][j][d];
            const u64* kp = (const u64*)&eks[s][j][d];
            const u64 v01 = vp[0], v23 = vp[1], k01 = kp[0], k23 = kp[1];
            #pragma unroll
            for (int ii = 0; ii < 4; ++ii) {
                const float e = eBs[s][i0 + ii][j];
                const u64 E = pack2(e, e);
                ffma2(aN[ii][0], E, v01); ffma2(aN[ii][1], E, v23);
                ffma2(aD[ii][0], E, k01); ffma2(aD[ii][1], E, k23);
            }
        }
        __syncthreads();
    }

    const int pbase = jx * SZ;
    #pragma unroll
    for (int ii = 0; ii < 4; ++ii) {
        const int gi = it0 + i0 + ii;
        const int off = (b*NN + gi)*DD + d0 + d;
        const float2 n01 = unpack2(aN[ii][0]), n23 = unpack2(aN[ii][1]);
        const float2 q01 = unpack2(aD[ii][0]), q23 = unpack2(aD[ii][1]);
        *(float4*)&g_pn[pbase + off] = make_float4(n01.x, n01.y, n23.x, n23.y);
        *(float4*)&g_pd[pbase + off] = make_float4(q01.x, q01.y, q23.x, q23.y);
    }
}

// ---------------- K3: reduce partials + epilogue ----------------
// 32768 threads, one float4 per thread.
__global__ __launch_bounds__(256) void reduce_kernel(float* __restrict__ out)
{
    const int off = (blockIdx.x * 256 + threadIdx.x) * 4;
    float4 n = *(const float4*)&g_pn[off];
    float4 dn = *(const float4*)&g_pd[off];
    #pragma unroll
    for (int js = 1; js < JS; ++js) {
        const float4 a = *(const float4*)&g_pn[js*SZ + off];
        const float4 c = *(const float4*)&g_pd[js*SZ + off];
        n.x += a.x; n.y += a.y; n.z += a.z; n.w += a.w;
        dn.x += c.x; dn.y += c.y; dn.z += c.z; dn.w += c.w;
    }
    const float4 sq = *(const float4*)&g_sq[off];
    float4 o;
    o.x = sq.x * __fdividef(n.x, dn.x);
    o.y = sq.y * __fdividef(n.y, dn.y);
    o.z = sq.z * __fdividef(n.z, dn.z);
    o.w = sq.w * __fdividef(n.w, dn.w);
    *(float4*)&out[off] = o;
}

// ---------------- launch ----------------
extern "C" void kernel_launch(void* const* d_in, const int* in_sizes, int n_in,
                              void* d_out, int out_size)
{
    const float* x  = (const float*)d_in[0];
    const float* Wq = (const float*)d_in[1];
    const float* bq = (const float*)d_in[2];
    const float* Wk = (const float*)d_in[3];
    const float* bk = (const float*)d_in[4];
    const float* Wv = (const float*)d_in[5];
    const float* bv = (const float*)d_in[6];
    const float* B  = (const float*)d_in[7];
    float* out = (float*)d_out;

    proj_kernel<<<dim3(64, 3), 256>>>(x, Wq, bq, Wk, bk, Wv, bv, B);
    aft_kernel<<<dim3(64, 2, 2), 128>>>();
    reduce_kernel<<<SZ/4/256, 256>>>(out);
}

// round 7
// speedup vs baseline: 1.5576x; 1.5576x over previous
#include <cuda_runtime.h>
#include <cuda_bf16.h>

#define BS 2
#define NN 512
#define DD 128
#define JS 4            // j-splits in main GEMM
#define SZ (BS*NN*DD)   // 131072

typedef unsigned long long u64;

// ---------------- device scratch (no allocs allowed) ----------------
__device__ float g_sq[SZ];         // sigmoid(q)
__device__ float g_ek[SZ];         // exp(k)   (|k| <~ 5, safe unshifted)
__device__ float g_v [SZ];         // raw v
__device__ float g_eB[NN*NN];      // exp(B)   (B ~ +-0.06)
__device__ float g_pn[JS*SZ];      // partial numerators
__device__ float g_pd[JS*SZ];      // partial denominators

// ---------------- f32x2 + cp.async helpers ----------------
__device__ __forceinline__ u64 pack2(float lo, float hi) {
    u64 r; asm("mov.b64 %0, {%1, %2};" : "=l"(r) : "f"(lo), "f"(hi)); return r;
}
__device__ __forceinline__ void ffma2(u64 &acc, u64 a, u64 b) {
    asm("fma.rn.f32x2 %0, %1, %2, %0;" : "+l"(acc) : "l"(a), "l"(b));
}
__device__ __forceinline__ u64 mul2(u64 a, u64 b) {
    u64 r; asm("mul.rn.f32x2 %0, %1, %2;" : "=l"(r) : "l"(a), "l"(b)); return r;
}
__device__ __forceinline__ float2 unpack2(u64 v) {
    float lo, hi; asm("mov.b64 {%0, %1}, %2;" : "=f"(lo), "=f"(hi) : "l"(v));
    return make_float2(lo, hi);
}
__device__ __forceinline__ void cp16(void* sdst, const void* gsrc) {
    unsigned s = (unsigned)__cvta_generic_to_shared(sdst);
    asm volatile("cp.async.ca.shared.global [%0], [%1], 16;" :: "r"(s), "l"(gsrc));
}
__device__ __forceinline__ void cp_commit() { asm volatile("cp.async.commit_group;"); }
template<int NPEND> __device__ __forceinline__ void cp_wait() {
    asm volatile("cp.async.wait_group %0;" :: "n"(NPEND));
}

// ---------------- K1: q/k/v projections + eB, all parallel ----------------
// grid (64, 4), 256 threads.
//   y=0: q GEMM  -> sigmoid -> g_sq
//   y=1: k GEMM  -> exp     -> g_ek
//   y=2: v GEMM  -> raw     -> g_v
//   y=3: eB = exp(B) elementwise
__global__ __launch_bounds__(256) void proj_kernel(
    const float* __restrict__ x,
    const float* __restrict__ Wq, const float* __restrict__ bq,
    const float* __restrict__ Wk, const float* __restrict__ bk,
    const float* __restrict__ Wv, const float* __restrict__ bv,
    const float* __restrict__ Bm)
{
    __shared__ float xs[16*128];
    __shared__ float Ws[2][32*128];
    const int mat = blockIdx.y;
    const int tid = threadIdx.x;

    if (mat == 3) {
        #pragma unroll
        for (int r = 0; r < 4; ++r) {
            const int off = blockIdx.x * 4096 + r * 1024 + tid * 4;
            const float4 b4 = *(const float4*)&Bm[off];
            float4 e;
            e.x = __expf(b4.x); e.y = __expf(b4.y);
            e.z = __expf(b4.z); e.w = __expf(b4.w);
            *(float4*)&g_eB[off] = e;
        }
        return;
    }

    const float* W    = (mat==0) ? Wq : ((mat==1) ? Wk : Wv);
    const float* bias = (mat==0) ? bq : ((mat==1) ? bk : bv);
    const int row0 = blockIdx.x * 16;
    const int dt = tid & 31, rt = tid >> 5;   // rt 0..7
    const int d = dt * 4;

    for (int q = tid; q < 16*128/4; q += 256) cp16(&xs[q*4], &x[row0*128 + q*4]);
    for (int q = tid; q < 32*128/4; q += 256) cp16(&Ws[0][q*4], &W[q*4]);
    cp_commit();

    const float4 bb = *(const float4*)&bias[d];
    u64 a00 = pack2(bb.x, bb.y), a01 = pack2(bb.z, bb.w);
    u64 a10 = a00, a11 = a01;

    for (int cc = 0; cc < 128; cc += 32) {
        const int s = (cc >> 5) & 1;
        if (cc + 32 < 128) {
            const int sn = s ^ 1;
            const float* Wn = &W[(cc + 32) * 128];
            for (int q = tid; q < 32*128/4; q += 256) cp16(&Ws[sn][q*4], &Wn[q*4]);
            cp_commit();
            cp_wait<1>();
        } else {
            cp_wait<0>();
        }
        __syncthreads();
        #pragma unroll
        for (int c = 0; c < 32; ++c) {
            const u64* wrow = (const u64*)&Ws[s][c*128 + d];
            const u64 w01 = wrow[0], w23 = wrow[1];
            const float x0 = xs[rt*128 + cc + c];        // broadcast LDS
            const float x1 = xs[(rt+8)*128 + cc + c];
            const u64 X0 = pack2(x0, x0), X1 = pack2(x1, x1);
            ffma2(a00, X0, w01); ffma2(a01, X0, w23);
            ffma2(a10, X1, w01); ffma2(a11, X1, w23);
        }
        __syncthreads();
    }

    #pragma unroll
    for (int r = 0; r < 2; ++r) {
        const int grow = row0 + ((r == 0) ? rt : (rt + 8));
        const float2 p = unpack2(r ? a10 : a00);
        const float2 q2 = unpack2(r ? a11 : a01);
        float4 o = make_float4(p.x, p.y, q2.x, q2.y);
        if (mat == 0) {
            o.x = 1.f/(1.f+__expf(-o.x)); o.y = 1.f/(1.f+__expf(-o.y));
            o.z = 1.f/(1.f+__expf(-o.z)); o.w = 1.f/(1.f+__expf(-o.w));
            *(float4*)&g_sq[grow*128 + d] = o;
        } else if (mat == 1) {
            o.x = __expf(o.x); o.y = __expf(o.y);
            o.z = __expf(o.z); o.w = __expf(o.w);
            *(float4*)&g_ek[grow*128 + d] = o;
        } else {
            *(float4*)&g_v[grow*128 + d] = o;
        }
    }
}

// ---------------- K2: partial GEMM  pn|pd += eB @ (ek*v | ek) ----------------
// grid (64, 2, 2): x = itile(16)*js(4), y = 64-d half, z = batch. 128 threads.
// CTA tile: 32 i x 64 d x 128 j. Thread tile: 4 i x 4 d, 16 f32x2 accumulators.
// ev = ek*v computed on the fly (2 mul.f32x2 per j, amortized over 4 i's).
__global__ __launch_bounds__(128) void aft_kernel()
{
    __shared__ float eBs[2][32][36];   // [i][j] padded
    __shared__ float vvs[2][32][64];   // raw v
    __shared__ float eks[2][32][64];   // exp(k)
    const int jx  = blockIdx.x & 3;
    const int it0 = (blockIdx.x >> 2) * 32;
    const int jb  = jx * 128;
    const int d0  = blockIdx.y * 64;
    const int b   = blockIdx.z;
    const int tid = threadIdx.x;
    const int dt = tid & 15, rt = tid >> 4;
    const int d = dt * 4;
    const int i0 = rt * 4;
    const float* vb  = g_v  + b*NN*DD + d0;
    const float* ekb = g_ek + b*NN*DD + d0;

    u64 aN[4][2], aD[4][2];
    #pragma unroll
    for (int ii = 0; ii < 4; ++ii) {
        aN[ii][0] = 0; aN[ii][1] = 0; aD[ii][0] = 0; aD[ii][1] = 0;
    }

    auto stage = [&](int s, int jc) {
        #pragma unroll
        for (int q = 0; q < 4; ++q) {
            const int e = tid + q*128;
            const int j = e >> 4, dd = (e & 15) * 4;
            cp16(&vvs[s][j][dd], &vb[(jb + jc + j)*DD + dd]);
            cp16(&eks[s][j][dd], &ekb[(jb + jc + j)*DD + dd]);
        }
        const int ri = tid >> 2, c4 = (tid & 3) * 4;
        const float* src = &g_eB[(it0 + ri)*NN + jb + jc];
        cp16(&eBs[s][ri][c4],      &src[c4]);
        cp16(&eBs[s][ri][c4 + 16], &src[c4 + 16]);
    };

    stage(0, 0);
    cp_commit();

    for (int m = 0; m < 4; ++m) {
        const int s = m & 1;
        if (m + 1 < 4) { stage(s ^ 1, (m + 1)*32); cp_commit(); cp_wait<1>(); }
        else           { cp_wait<0>(); }
        __syncthreads();
        #pragma unroll 8
        for (int j = 0; j < 32; ++j) {
            const u64* vp = (const u64*)&vvs[s][j][d];
            const u64* kp = (const u64*)&eks[s][j][d];
            const u64 v01 = vp[0], v23 = vp[1], k01 = kp[0], k23 = kp[1];
            const u64 ev01 = mul2(k01, v01), ev23 = mul2(k23, v23);
            #pragma unroll
            for (int ii = 0; ii < 4; ++ii) {
                const float e = eBs[s][i0 + ii][j];
                const u64 E = pack2(e, e);
                ffma2(aN[ii][0], E, ev01); ffma2(aN[ii][1], E, ev23);
                ffma2(aD[ii][0], E, k01);  ffma2(aD[ii][1], E, k23);
            }
        }
        __syncthreads();
    }

    const int pbase = jx * SZ;
    #pragma unroll
    for (int ii = 0; ii < 4; ++ii) {
        const int gi = it0 + i0 + ii;
        const int off = (b*NN + gi)*DD + d0 + d;
        const float2 n01 = unpack2(aN[ii][0]), n23 = unpack2(aN[ii][1]);
        const float2 q01 = unpack2(aD[ii][0]), q23 = unpack2(aD[ii][1]);
        *(float4*)&g_pn[pbase + off] = make_float4(n01.x, n01.y, n23.x, n23.y);
        *(float4*)&g_pd[pbase + off] = make_float4(q01.x, q01.y, q23.x, q23.y);
    }
}

// ---------------- K3: reduce partials + epilogue ----------------
__global__ __launch_bounds__(256) void reduce_kernel(float* __restrict__ out)
{
    const int off = (blockIdx.x * 256 + threadIdx.x) * 4;
    float4 n = *(const float4*)&g_pn[off];
    float4 dn = *(const float4*)&g_pd[off];
    #pragma unroll
    for (int js = 1; js < JS; ++js) {
        const float4 a = *(const float4*)&g_pn[js*SZ + off];
        const float4 c = *(const float4*)&g_pd[js*SZ + off];
        n.x += a.x; n.y += a.y; n.z += a.z; n.w += a.w;
        dn.x += c.x; dn.y += c.y; dn.z += c.z; dn.w += c.w;
    }
    const float4 sq = *(const float4*)&g_sq[off];
    float4 o;
    o.x = sq.x * __fdividef(n.x, dn.x);
    o.y = sq.y * __fdividef(n.y, dn.y);
    o.z = sq.z * __fdividef(n.z, dn.z);
    o.w = sq.w * __fdividef(n.w, dn.w);
    *(float4*)&out[off] = o;
}

// ---------------- launch ----------------
extern "C" void kernel_launch(void* const* d_in, const int* in_sizes, int n_in,
                              void* d_out, int out_size)
{
    const float* x  = (const float*)d_in[0];
    const float* Wq = (const float*)d_in[1];
    const float* bq = (const float*)d_in[2];
    const float* Wk = (const float*)d_in[3];
    const float* bk = (const float*)d_in[4];
    const float* Wv = (const float*)d_in[5];
    const float* bv = (const float*)d_in[6];
    const float* B  = (const float*)d_in[7];
    float* out = (float*)d_out;

    proj_kernel<<<dim3(64, 4), 256>>>(x, Wq, bq, Wk, bk, Wv, bv, B);
    aft_kernel<<<dim3(64, 2, 2), 128>>>();
    reduce_kernel<<<SZ/4/256, 256>>>(out);
}